// round 17
// baseline (speedup 1.0000x reference)
#include <cuda_runtime.h>
#include <cuda_bf16.h>
#include <cuda_fp16.h>
#include <math.h>

#define NROWS 384
#define SLEN  1024
#define CIN   256
#define CH    32
#define NH    8
#define HC    256   // NH*CH

// Scratch (no cudaMalloc allowed).
__device__ float g_q_buf[NROWS * HC];
__device__ float g_o_buf[NROWS * HC];
__device__ float g_k_buf[(size_t)NROWS * SLEN * CH];
__device__ float g_v_buf[(size_t)NROWS * SLEN * CH];
// Weights, all fp16 single-MMA paths (error budget calibrated R12-R16):
__device__ __half g_Wg16[CIN * HC];
__device__ __half g_Wo16[HC * CIN];
__device__ __half g_Wkv16[CIN * 64];          // Wk|Wv combined, [K,64]
// Masked-mean partials: [tile 0..15][n][c] and [tile][n]
__device__ float g_qpart[16 * NROWS * CIN];
__device__ float g_mpart[16 * NROWS];
// Split-S attention partials: [quarter][n][hc] and stats [quarter][n][h][2]
__device__ float g_opart[4 * NROWS * HC];
__device__ float g_stat[4 * NROWS * NH * 2];

// ---------------------------------------------------------------------------
// cp.async helpers
// ---------------------------------------------------------------------------
__device__ __forceinline__ void cp16(unsigned saddr, const void* g) {
    asm volatile("cp.async.cg.shared.global [%0], [%1], 16;" :: "r"(saddr), "l"(g));
}
#define CP_COMMIT() asm volatile("cp.async.commit_group;" ::: "memory")
#define CP_WAIT1()  asm volatile("cp.async.wait_group 1;" ::: "memory")
#define CP_WAIT0()  asm volatile("cp.async.wait_group 0;" ::: "memory")

// ---------------------------------------------------------------------------
// Kernel 0: weight conversion (all fp16)
// ---------------------------------------------------------------------------
__global__ void wconv_kernel(const float* __restrict__ Wg,
                             const float* __restrict__ Wo,
                             const float* __restrict__ Wk,
                             const float* __restrict__ Wv) {
    int i = (blockIdx.x * 256 + threadIdx.x) * 4;  // 65536 elems per big matrix
    {
        float4 v = *reinterpret_cast<const float4*>(Wg + i);
        *reinterpret_cast<__half2*>(g_Wg16 + i)     = __floats2half2_rn(v.x, v.y);
        *reinterpret_cast<__half2*>(g_Wg16 + i + 2) = __floats2half2_rn(v.z, v.w);
    }
    {
        float4 v = *reinterpret_cast<const float4*>(Wo + i);
        *reinterpret_cast<__half2*>(g_Wo16 + i)     = __floats2half2_rn(v.x, v.y);
        *reinterpret_cast<__half2*>(g_Wo16 + i + 2) = __floats2half2_rn(v.z, v.w);
    }
    if (i < CIN * 64) {  // combined Wk|Wv: row k, col j (j<32 => Wk, else Wv)
        int k = i >> 6, j = i & 63;
        float4 v = (j < 32)
            ? *reinterpret_cast<const float4*>(Wk + k * CH + j)
            : *reinterpret_cast<const float4*>(Wv + k * CH + (j - 32));
        *reinterpret_cast<__half2*>(g_Wkv16 + i)     = __floats2half2_rn(v.x, v.y);
        *reinterpret_cast<__half2*>(g_Wkv16 + i + 2) = __floats2half2_rn(v.z, v.w);
    }
}

// ---------------------------------------------------------------------------
// mma helpers
// ---------------------------------------------------------------------------
__device__ __forceinline__ void ldsm4(unsigned r[4], unsigned addr) {
    asm volatile("ldmatrix.sync.aligned.m8n8.x4.shared.b16 {%0,%1,%2,%3}, [%4];"
        : "=r"(r[0]), "=r"(r[1]), "=r"(r[2]), "=r"(r[3]) : "r"(addr));
}
__device__ __forceinline__ void ldsm4t(unsigned r[4], unsigned addr) {
    asm volatile("ldmatrix.sync.aligned.m8n8.x4.trans.shared.b16 {%0,%1,%2,%3}, [%4];"
        : "=r"(r[0]), "=r"(r[1]), "=r"(r[2]), "=r"(r[3]) : "r"(addr));
}
__device__ __forceinline__ void mma_fp16(float c[4], const unsigned a[4],
                                         unsigned b0, unsigned b1) {
    asm volatile("mma.sync.aligned.m16n8k16.row.col.f32.f16.f16.f32 "
        "{%0,%1,%2,%3}, {%4,%5,%6,%7}, {%8,%9}, {%0,%1,%2,%3};"
        : "+f"(c[0]), "+f"(c[1]), "+f"(c[2]), "+f"(c[3])
        : "r"(a[0]), "r"(a[1]), "r"(a[2]), "r"(a[3]), "r"(b0), "r"(b1));
}

// ---------------------------------------------------------------------------
// Kernel 2: k|v = m @ (Wk|Wv), fp16 single-MMA + fused masked-mean partials.
// (unchanged from R16 — passing)
// ---------------------------------------------------------------------------
#define KA_STR  264
#define KB_STR  72
#define KB0_OFF 33792             // stage s at KB0 + s*2304 (fp16 [16][64])
#define KV_SMEM 38400

__device__ __forceinline__ void kv_prefetch(unsigned sbase, int stage, int kk, int t) {
    if (t < 128) {
        int row = t >> 3, c8 = (t & 7) << 3;
        cp16(sbase + KB0_OFF + stage * 2304 + (row * KB_STR + c8) * 2,
             g_Wkv16 + (kk + row) * 64 + c8);
    }
}

__global__ void __launch_bounds__(256, 3)
kv_kernel(const float* __restrict__ m, const float* __restrict__ mask) {
    extern __shared__ char smc[];
    __shared__ float mask_sm[64];
    unsigned sbase = (unsigned)__cvta_generic_to_shared(smc);
    int t = threadIdx.x;
    int lane = t & 31, wid = t >> 5;
    int wm = wid >> 1, wn = wid & 1;
    int n    = blockIdx.x >> 4;
    int tile = blockIdx.x & 15;
    long r0g = (long)blockIdx.x * 64;

    if (t < 64) mask_sm[t] = mask[(size_t)n * SLEN + tile * 64 + t];

    // load m tile [64][256] fp32 -> fp16 smem
    #pragma unroll
    for (int i = 0; i < 16; i++) {
        int idx = t + i * 256;
        int row = idx >> 6;
        int c4  = (idx & 63) << 2;
        float4 v = *reinterpret_cast<const float4*>(m + (r0g + row) * CIN + c4);
        char* p = smc + (row * KA_STR + c4) * 2;
        reinterpret_cast<__half2*>(p)[0] = __floats2half2_rn(v.x, v.y);
        reinterpret_cast<__half2*>(p)[1] = __floats2half2_rn(v.z, v.w);
    }
    __syncthreads();

    kv_prefetch(sbase, 0, 0, t);
    CP_COMMIT();

    // masked-mean partial for channel t over this CTA's 64 tokens
    {
        float qs = 0.f;
        #pragma unroll 8
        for (int r = 0; r < 64; r++) {
            float mv = __half2float(*reinterpret_cast<__half*>(
                smc + (r * KA_STR + t) * 2));
            qs = fmaf(mv, mask_sm[r], qs);
        }
        g_qpart[(tile * NROWS + n) * CIN + t] = qs;
        if (t == 0) {
            float ms = 0.f;
            for (int r = 0; r < 64; r++) ms += mask_sm[r];
            g_mpart[tile * NROWS + n] = ms;
        }
    }

    float acc[4][4];
    #pragma unroll
    for (int i = 0; i < 4; i++)
        #pragma unroll
        for (int j = 0; j < 4; j++) acc[i][j] = 0.f;

    for (int c = 0; c < 16; c++) {
        CP_WAIT0();
        __syncthreads();
        if (c < 15) { kv_prefetch(sbase, (c + 1) & 1, (c + 1) * 16, t); CP_COMMIT(); }
        int kk = c * 16;
        unsigned kbh = sbase + KB0_OFF + (c & 1) * 2304;

        unsigned a16[4];
        unsigned aaddr = sbase +
            ((wm * 16 + (lane & 15)) * KA_STR + kk + ((lane >> 4) << 3)) * 2;
        ldsm4(a16, aaddr);

        #pragma unroll
        for (int nb = 0; nb < 2; nb++) {
            int col0 = wn * 32 + nb * 16;
            unsigned baddr = kbh +
                ((lane & 15) * KB_STR + col0 + ((lane >> 4) << 3)) * 2;
            unsigned bh[4];
            ldsm4t(bh, baddr);
            mma_fp16(acc[nb * 2],     a16, bh[0], bh[1]);
            mma_fp16(acc[nb * 2 + 1], a16, bh[2], bh[3]);
        }
    }

    // write k (cols 0..31) and v (cols 32..63)
    #pragma unroll
    for (int nb = 0; nb < 2; nb++) {
        #pragma unroll
        for (int half = 0; half < 2; half++) {
            int col = wn * 32 + nb * 16 + half * 8 + (lane & 3) * 2;
            int r0  = wm * 16 + (lane >> 2);
            float* f = acc[nb * 2 + half];
            float* dst = (col < CH) ? (g_k_buf + ((r0g + r0) * CH + col))
                                    : (g_v_buf + ((r0g + r0) * CH + col - CH));
            *reinterpret_cast<float2*>(dst) = make_float2(f[0], f[1]);
            dst += 8 * CH;
            *reinterpret_cast<float2*>(dst) = make_float2(f[2], f[3]);
        }
    }
}

// ---------------------------------------------------------------------------
// Kernel 2b: finish mean + q = (mean @ Wq) * C^-0.5
// ---------------------------------------------------------------------------
__global__ void q2_kernel(const float* __restrict__ Wq) {
    int n = blockIdx.x, t = threadIdx.x;
    __shared__ float qm[CIN];
    float s = 0.f;
    #pragma unroll
    for (int p = 0; p < 16; p++) s += g_qpart[(p * NROWS + n) * CIN + t];
    float mk = 0.f;
    #pragma unroll
    for (int p = 0; p < 16; p++) mk += g_mpart[p * NROWS + n];
    qm[t] = s / (mk + 1e-10f);
    __syncthreads();
    float acc = 0.f;
    #pragma unroll 8
    for (int c = 0; c < CIN; c++) acc = fmaf(qm[c], Wq[c * HC + t], acc);
    g_q_buf[n * HC + t] = acc * 0.17677669529663687f;
}

// ---------------------------------------------------------------------------
// Kernel 3a: split-S attention partials, 4 quarters. grid (384, 4).
// ---------------------------------------------------------------------------
#define S4 256

__global__ void __launch_bounds__(256)
attn_part_kernel(const float* __restrict__ mask) {
    int n = blockIdx.x, qt = blockIdx.y, t = threadIdx.x;
    int s0 = qt * S4;
    __shared__ float q_sm[HC];
    __shared__ float p_sm[NH * S4];   // 8 KB

    q_sm[t] = g_q_buf[n * HC + t];
    __syncthreads();

    const float* krow = g_k_buf + ((size_t)n * SLEN + s0) * CH;
    const float* vrow = g_v_buf + ((size_t)n * SLEN + s0) * CH;
    const float* mk   = mask + (size_t)n * SLEN + s0;

    {
        int s = t;
        float kreg[32];
        #pragma unroll
        for (int q = 0; q < 8; q++)
            *reinterpret_cast<float4*>(kreg + q * 4) =
                *reinterpret_cast<const float4*>(krow + (size_t)s * CH + q * 4);
        float bias = 1e9f * (mk[s] - 1.0f);
        #pragma unroll
        for (int h = 0; h < NH; h++) {
            float d = 0.f;
            #pragma unroll
            for (int j = 0; j < 32; j++) d = fmaf(q_sm[h * 32 + j], kreg[j], d);
            p_sm[h * S4 + s] = d + bias;
        }
    }
    __syncthreads();

    int h = t >> 5, lane = t & 31;
    float mx = -3.0e38f;
    for (int s = lane; s < S4; s += 32) mx = fmaxf(mx, p_sm[h * S4 + s]);
    #pragma unroll
    for (int off = 16; off > 0; off >>= 1)
        mx = fmaxf(mx, __shfl_xor_sync(0xffffffffu, mx, off));

    float sum = 0.f;
    for (int s = lane; s < S4; s += 32) {
        float e = __expf(p_sm[h * S4 + s] - mx);
        p_sm[h * S4 + s] = e;
        sum += e;
    }
    #pragma unroll
    for (int off = 16; off > 0; off >>= 1)
        sum += __shfl_xor_sync(0xffffffffu, sum, off);
    if (lane == 0) {
        g_stat[((qt * NROWS + n) * NH + h) * 2]     = mx;
        g_stat[((qt * NROWS + n) * NH + h) * 2 + 1] = sum;
    }
    __syncthreads();

    // unnormalized p@v partial
    {
        int sg  = lane >> 3;
        int c4  = (lane & 7) << 2;
        float4 acc4 = make_float4(0.f, 0.f, 0.f, 0.f);
        const float* ph = p_sm + h * S4;
        #pragma unroll 4
        for (int s = sg; s < S4; s += 4) {
            float p = ph[s];
            float4 v4 = *reinterpret_cast<const float4*>(vrow + (size_t)s * CH + c4);
            acc4.x = fmaf(p, v4.x, acc4.x);
            acc4.y = fmaf(p, v4.y, acc4.y);
            acc4.z = fmaf(p, v4.z, acc4.z);
            acc4.w = fmaf(p, v4.w, acc4.w);
        }
        #pragma unroll
        for (int off = 8; off <= 16; off <<= 1) {
            acc4.x += __shfl_xor_sync(0xffffffffu, acc4.x, off);
            acc4.y += __shfl_xor_sync(0xffffffffu, acc4.y, off);
            acc4.z += __shfl_xor_sync(0xffffffffu, acc4.z, off);
            acc4.w += __shfl_xor_sync(0xffffffffu, acc4.w, off);
        }
        if (sg == 0)
            *reinterpret_cast<float4*>(
                g_opart + (qt * NROWS + n) * HC + h * CH + c4) = acc4;
    }
}

// ---------------------------------------------------------------------------
// Kernel 3b: merge the four S-quarters
// ---------------------------------------------------------------------------
__global__ void attn_merge_kernel() {
    int n = blockIdx.x, t = threadIdx.x;
    int h = t >> 5;
    float mq[4], sq[4];
    #pragma unroll
    for (int p = 0; p < 4; p++) {
        mq[p] = g_stat[((p * NROWS + n) * NH + h) * 2];
        sq[p] = g_stat[((p * NROWS + n) * NH + h) * 2 + 1];
    }
    float M = fmaxf(fmaxf(mq[0], mq[1]), fmaxf(mq[2], mq[3]));
    float num = 0.f, den = 0.f;
    #pragma unroll
    for (int p = 0; p < 4; p++) {
        float w = __expf(mq[p] - M);
        num = fmaf(w, g_opart[(p * NROWS + n) * HC + t], num);
        den = fmaf(w, sq[p], den);
    }
    g_o_buf[n * HC + t] = num / den;
}

// ---------------------------------------------------------------------------
// Kernel 4: out_kernel, fp16 single-MMA, BK=32, 3-stage WARP-LOCAL cp.async.
// 1x8 warp layout: each warp owns all 64 rows x a private 32-col slice, and
// prefetches its own B slice (per-warp smem region, per-warp groups).  The
// GEMM mainloop has ZERO __syncthreads (A tile is read-only during it).
// BM=64, 256 threads, 2 CTAs/SM, ~96 KB smem.
// ---------------------------------------------------------------------------
#define A_STR   264
#define AH_OFF  0                 // fp16 m tile, then fp16 G tile (33792 B)
#define B0_OFF  33792             // (stage*8 + warp)*2560; [32 rows][40 halfs]
#define BW_STR  40                // B row stride in halfs (80 B, conflict-free)
#define BW_SZ   2560              // one warp-stage: 32*40*2
#define BG_OFF  95232
#define OV_OFF  96256
#define BO_OFF  97280
#define SMEM_BYTES 98304

// Warp-local prefetch of this warp's B slice for chunk kk: 32 rows x 32 cols.
// Lane = row; each lane copies its 64-byte row as 4 cp16.
__device__ __forceinline__ void owp_prefetch(unsigned sbase, int stage,
        const __half* __restrict__ W16, int kk, int wid, int wn, int lane) {
    unsigned dst = sbase + B0_OFF + (stage * 8 + wid) * BW_SZ + lane * (BW_STR * 2);
    const __half* src = W16 + (kk + lane) * 256 + wn * 32;
    #pragma unroll
    for (int i = 0; i < 4; i++)
        cp16(dst + i * 16, src + i * 8);
}

// One 64x256x256 fp16 GEMM, BK=32, 3-stage per-warp pipeline, no barriers.
__device__ __forceinline__ void gemm_fp16x1(
    unsigned sbase, const __half* __restrict__ W16,
    float acc[16][4], int wid, int wn, int lane, bool pre0,
    const __half* __restrict__ Wnext)
{
    if (!pre0) { owp_prefetch(sbase, 0, W16, 0, wid, wn, lane); CP_COMMIT(); }
    owp_prefetch(sbase, 1, W16, 32, wid, wn, lane); CP_COMMIT();
    for (int c = 0; c < 8; c++) {
        if (c == 7) CP_WAIT0();   // chunk 7's group may be the only one pending
        else        CP_WAIT1();   // chunk c done; chunk c+1 may stay in flight
        if (c < 6) { owp_prefetch(sbase, (c + 2) % 3, W16, (c + 2) * 32, wid, wn, lane); CP_COMMIT(); }
        else if (c == 7 && Wnext) { owp_prefetch(sbase, 0, Wnext, 0, wid, wn, lane); CP_COMMIT(); }
        unsigned bstage = sbase + B0_OFF + ((c % 3) * 8 + wid) * BW_SZ;

        #pragma unroll
        for (int hkk = 0; hkk < 2; hkk++) {
            int kk = c * 32 + hkk * 16;
            // A: 4 m16 fragments covering all 64 rows
            unsigned a[4][4];
            #pragma unroll
            for (int f = 0; f < 4; f++)
                ldsm4(a[f], sbase + AH_OFF +
                    ((f * 16 + (lane & 15)) * A_STR + kk + ((lane >> 4) << 3)) * 2);
            // B: 2 n16 fragments from this warp's private slice
            #pragma unroll
            for (int j = 0; j < 2; j++) {
                unsigned b[4];
                ldsm4t(b, bstage +
                    ((hkk * 16 + (lane & 15)) * BW_STR + j * 16 + ((lane >> 4) << 3)) * 2);
                #pragma unroll
                for (int f = 0; f < 4; f++) {
                    mma_fp16(acc[f * 4 + j * 2],     a[f], b[0], b[1]);
                    mma_fp16(acc[f * 4 + j * 2 + 1], a[f], b[2], b[3]);
                }
            }
        }
    }
}

__global__ void __launch_bounds__(256, 2)
out_kernel(const float* __restrict__ m,
           const float* __restrict__ bg,
           const float* __restrict__ bo,
           float* __restrict__ out) {
    extern __shared__ char smc[];
    unsigned sbase = (unsigned)__cvta_generic_to_shared(smc);
    float* sBG = reinterpret_cast<float*>(smc + BG_OFF);
    float* sOV = reinterpret_cast<float*>(smc + OV_OFF);
    float* sBO = reinterpret_cast<float*>(smc + BO_OFF);

    int t = threadIdx.x;
    int lane = t & 31, wid = t >> 5;
    int wn = wid;                      // 1x8: warp = column slice [wn*32, wn*32+32)
    int n = blockIdx.y;
    long tok0 = (long)n * SLEN + (long)blockIdx.x * 64;

    sBG[t] = bg[t];
    sOV[t] = g_o_buf[n * HC + t];
    sBO[t] = bo[t];

    // warp-local prefetch of GEMM1 chunk 0/1 starts before the A load
    owp_prefetch(sbase, 0, g_Wg16, 0, wid, wn, lane); CP_COMMIT();

    // load m tile [64][256] fp32 once -> fp16 smem (GEMM1 operand)
    #pragma unroll
    for (int i = 0; i < 16; i++) {
        int idx = t + i * 256;
        int row = idx >> 6;
        int c4  = (idx & 63) << 2;
        float4 v = *reinterpret_cast<const float4*>(m + (tok0 + row) * CIN + c4);
        char* p = smc + AH_OFF + (row * A_STR + c4) * 2;
        reinterpret_cast<__half2*>(p)[0] = __floats2half2_rn(v.x, v.y);
        reinterpret_cast<__half2*>(p)[1] = __floats2half2_rn(v.z, v.w);
    }
    __syncthreads();

    float acc[16][4];
    #pragma unroll
    for (int i = 0; i < 16; i++)
        #pragma unroll
        for (int j = 0; j < 4; j++) acc[i][j] = 0.f;

    // ---- GEMM1: x = M @ Wg (chunk 0 committed above; tail prefetches Wo) ----
    gemm_fp16x1(sbase, g_Wg16, acc, wid, wn, lane, true, g_Wo16);
    __syncthreads();   // all warps done reading A (m tile) before rewrite

    // ---- epilogue 1: G = ov * sigmoid(acc + bg) -> fp16 A tile ----
    // acc[f*4 + j*2 + half]: rows f*16 + (lane>>2) + {0,8},
    // cols wn*32 + j*16 + half*8 + (lane&3)*2
    #pragma unroll
    for (int f = 0; f < 4; f++)
    #pragma unroll
    for (int j = 0; j < 2; j++)
    #pragma unroll
    for (int half = 0; half < 2; half++) {
        float* a = acc[f * 4 + j * 2 + half];
        int col0 = wn * 32 + j * 16 + half * 8 + (lane & 3) * 2;
        int r0   = f * 16 + (lane >> 2);
        float bg0 = sBG[col0], bg1 = sBG[col0 + 1];
        float ov0 = sOV[col0], ov1 = sOV[col0 + 1];
        float g0 = ov0 / (1.f + __expf(-(a[0] + bg0)));
        float g1 = ov1 / (1.f + __expf(-(a[1] + bg1)));
        float g2 = ov0 / (1.f + __expf(-(a[2] + bg0)));
        float g3 = ov1 / (1.f + __expf(-(a[3] + bg1)));
        *reinterpret_cast<__half2*>(smc + AH_OFF + (r0 * A_STR + col0) * 2)
            = __floats2half2_rn(g0, g1);
        *reinterpret_cast<__half2*>(smc + AH_OFF + ((r0 + 8) * A_STR + col0) * 2)
            = __floats2half2_rn(g2, g3);
        a[0] = a[1] = a[2] = a[3] = 0.f;
    }
    __syncthreads();   // G tile complete before GEMM2 reads it

    // ---- GEMM2: out = G @ Wo (chunk 0 already in flight) ----
    gemm_fp16x1(sbase, g_Wo16, acc, wid, wn, lane, true, (const __half*)0);

    // ---- epilogue 2: + bo, write out (no A rewrite -> no barrier needed) ----
    #pragma unroll
    for (int f = 0; f < 4; f++)
    #pragma unroll
    for (int j = 0; j < 2; j++)
    #pragma unroll
    for (int half = 0; half < 2; half++) {
        float* a = acc[f * 4 + j * 2 + half];
        int col0 = wn * 32 + j * 16 + half * 8 + (lane & 3) * 2;
        int r0   = f * 16 + (lane >> 2);
        float2 o0 = make_float2(a[0] + sBO[col0], a[1] + sBO[col0 + 1]);
        float2 o1 = make_float2(a[2] + sBO[col0], a[3] + sBO[col0 + 1]);
        *reinterpret_cast<float2*>(out + (tok0 + r0) * CIN + col0)     = o0;
        *reinterpret_cast<float2*>(out + (tok0 + r0 + 8) * CIN + col0) = o1;
    }
}

// ---------------------------------------------------------------------------
extern "C" void kernel_launch(void* const* d_in, const int* in_sizes, int n_in,
                              void* d_out, int out_size) {
    const float* m    = (const float*)d_in[0];
    const float* mask = (const float*)d_in[1];
    const float* Wq   = (const float*)d_in[2];
    const float* Wk   = (const float*)d_in[3];
    const float* Wv   = (const float*)d_in[4];
    const float* Wg   = (const float*)d_in[5];
    const float* bg   = (const float*)d_in[6];
    const float* Wo   = (const float*)d_in[7];
    const float* bo   = (const float*)d_in[8];
    float* out = (float*)d_out;

    wconv_kernel<<<64, 256>>>(Wg, Wo, Wk, Wv);

    cudaFuncSetAttribute(kv_kernel,
                         cudaFuncAttributeMaxDynamicSharedMemorySize, KV_SMEM);
    kv_kernel<<<(NROWS * SLEN) / 64, 256, KV_SMEM>>>(m, mask);

    q2_kernel<<<NROWS, 256>>>(Wq);

    attn_part_kernel<<<dim3(NROWS, 4), 256>>>(mask);
    attn_merge_kernel<<<NROWS, 256>>>();

    cudaFuncSetAttribute(out_kernel,
                         cudaFuncAttributeMaxDynamicSharedMemorySize, SMEM_BYTES);
    out_kernel<<<dim3(SLEN / 64, NROWS), 256, SMEM_BYTES>>>(m, bg, bo, out);
}